// round 10
// baseline (speedup 1.0000x reference)
#include <cuda_runtime.h>
#include <cuda_fp16.h>
#include <cstdint>
#include <cstddef>

#define N_ROWS 131072
#define DIM    512
#define NCLU   512

// ---------------------------------------------------------------------------
// Device-global scratch (centers only)
// ---------------------------------------------------------------------------
__device__ __half g_ch[(size_t)NCLU * DIM];
__device__ float g_c2[NCLU];

// ---------------------------------------------------------------------------
// Helpers
// ---------------------------------------------------------------------------
__device__ __forceinline__ uint32_t smem_to_u32(const void* smem_ptr) {
    uint32_t addr;
    asm("{ .reg .u64 tmp; cvta.to.shared.u64 tmp, %1; cvt.u32.u64 %0, tmp; }"
        : "=r"(addr) : "l"(smem_ptr));
    return addr;
}
__device__ __forceinline__ void cp16(uint32_t dst_smem, const void* src) {
    asm volatile("cp.async.cg.shared.global [%0], [%1], 16;"
                 :: "r"(dst_smem), "l"(src));
}
__device__ __forceinline__ void cp_commit() {
    asm volatile("cp.async.commit_group;");
}
template <int N>
__device__ __forceinline__ void cp_wait() {
    asm volatile("cp.async.wait_group %0;" :: "n"(N));
}
__device__ __forceinline__ float frcp(float a) {
    float r;
    asm("rcp.approx.f32 %0, %1;" : "=f"(r) : "f"(a));
    return r;
}
__device__ __forceinline__ void ldsm4(uint32_t* r, uint32_t addr) {
    asm volatile("ldmatrix.sync.aligned.m8n8.x4.shared.b16 {%0,%1,%2,%3}, [%4];"
                 : "=r"(r[0]), "=r"(r[1]), "=r"(r[2]), "=r"(r[3]) : "r"(addr));
}
// Pinned-issue global vector load (issued where placed)
__device__ __forceinline__ float4 ldg128(const float* p) {
    float4 v;
    asm volatile("ld.global.nc.v4.f32 {%0,%1,%2,%3}, [%4];"
                 : "=f"(v.x), "=f"(v.y), "=f"(v.z), "=f"(v.w) : "l"(p));
    return v;
}
__device__ __forceinline__ void sts_v2(uint32_t addr, uint32_t a, uint32_t b) {
    asm volatile("st.shared.v2.b32 [%0], {%1,%2};"
                 :: "r"(addr), "r"(a), "r"(b) : "memory");
}
__device__ __forceinline__ void mma16816h(uint32_t* c, const uint32_t* a, const uint32_t* b) {
    asm volatile(
        "mma.sync.aligned.m16n8k16.row.col.f16.f16.f16.f16 "
        "{%0,%1}, {%2,%3,%4,%5}, {%6,%7}, {%0,%1};"
        : "+r"(c[0]), "+r"(c[1])
        : "r"(a[0]), "r"(a[1]), "r"(a[2]), "r"(a[3]), "r"(b[0]), "r"(b[1]));
}
__device__ __forceinline__ uint32_t pack_f16(float a, float b) {
    union { __half2 h; uint32_t u; } pk;
    pk.h = __floats2half2_rn(a, b);
    return pk.u;
}

// ---------------------------------------------------------------------------
// Prep centers: fp32 -> fp16 + row norms (one row per warp). ~2us.
// ---------------------------------------------------------------------------
__global__ void prep_c_kernel(const float* __restrict__ c) {
    int row = blockIdx.x * 8 + (threadIdx.x >> 5);
    if (row >= NCLU) return;
    int lane = threadIdx.x & 31;
    const float4* sr = (const float4*)(c + (size_t)row * DIM);
    uint2* dr = (uint2*)(g_ch + (size_t)row * DIM);
    float s = 0.f;
    #pragma unroll
    for (int t = 0; t < 4; t++) {
        float4 v = sr[lane + 32 * t];
        s += v.x * v.x + v.y * v.y + v.z * v.z + v.w * v.w;
        uint2 u;
        u.x = pack_f16(v.x, v.y);
        u.y = pack_f16(v.z, v.w);
        dr[lane + 32 * t] = u;
    }
    #pragma unroll
    for (int o = 16; o; o >>= 1) s += __shfl_xor_sync(0xffffffffu, s, o);
    if (lane == 0) g_c2[row] = s;
}

// ---------------------------------------------------------------------------
// Fused GEMM + t-student epilogue.
// 256 threads, 8 warps (2m x 4n), warp tile 64x64, CTA tile 128x256.
// Cluster of 2 CTAs covers the 512 clusters of one 128-row tile (row sums
// exchanged via DSMEM). Small CTA + ~111KB smem -> 2 CTAs/SM: two
// independent barrier domains hide each other's sync/convert phases.
// A path: pinned LDG.128 (fp32) -> registers -> cvt fp16 -> STS into the
// double-buffered Ahf tile. ||x||^2 exact fp32 from the same registers.
// ---------------------------------------------------------------------------
static constexpr int TM = 128, TN = 256, KC = 64, NUM_KC = DIM / KC;  // 8
static constexpr int AHF_BYTES = TM * KC * 2;              // 16384 / buf
static constexpr int B_BYTES   = TN * KC * 2;              // 32768 / stage
static constexpr int AHF_OFF  = 0;                          // 2 bufs
static constexpr int B_OFF    = 2 * AHF_BYTES;              // 32768, 2 stages
static constexpr int C2_OFF   = B_OFF + 2 * B_BYTES;        // 98304 (256 cols)
static constexpr int X2P_OFF  = C2_OFF + TN * 4;            // 99328 (128x16)
static constexpr int X2_OFF   = X2P_OFF + TM * 16 * 4;      // 107520
static constexpr int RED_OFF  = X2_OFF + TM * 4;            // 108032 (128x4)
static constexpr int PEER_OFF = RED_OFF + TM * 4 * 4;       // 110080
static constexpr int INV_OFF  = PEER_OFF + TM * 4;          // 110592
static constexpr int SMEM_TOTAL = INV_OFF + TM * 4;         // 111104

__global__ void __launch_bounds__(256, 2) __cluster_dims__(2, 1, 1)
gemm_kernel(const float* __restrict__ x, float* __restrict__ out) {
    extern __shared__ __align__(1024) char smem[];
    uint32_t sb = smem_to_u32(smem);
    int tid = threadIdx.x;
    int wid = tid >> 5, lane = tid & 31;
    int mtile = blockIdx.x >> 1;
    int nhalf = blockIdx.x & 1;
    int warp_m = wid & 1;        // 2 x 64 rows
    int warp_n = wid >> 1;       // 4 x 64 cols

    float* c2s  = (float*)(smem + C2_OFF);
    float* x2p  = (float*)(smem + X2P_OFF);
    float* x2s  = (float*)(smem + X2_OFF);
    float* red  = (float*)(smem + RED_OFF);
    float* peer = (float*)(smem + PEER_OFF);
    float* invs = (float*)(smem + INV_OFF);

    for (int i = tid; i < TN; i += 256) c2s[i] = g_c2[nhalf * TN + i];

    const float* asrc0 = x + (size_t)mtile * TM * DIM;
    const __half* bsrc0 = g_ch + (size_t)nhalf * TN * DIM;

    // A ownership: 2048 16B-chunks/kc, 8 per thread.
    // chunk(i): row = (tid>>4) + 16*i, col-quarter cpos = tid&15 (fp32 x4)
    int r0 = tid >> 4, cpos = tid & 15;

    auto load_B = [&](int kc, int s) {
        uint32_t Bb = sb + B_OFF + s * B_BYTES;
        const __half* bsrc = bsrc0 + kc * KC;
        #pragma unroll
        for (int i = 0; i < 8; i++) {       // 2048 chunks
            int idx = tid + i * 256;
            int r = idx >> 3, c = idx & 7;
            cp16(Bb + r * 128 + ((c * 16) ^ ((r & 7) << 4)),
                 bsrc + (size_t)r * DIM + c * 8);
        }
        cp_commit();
    };

    float4 w[4];          // in-flight A fp32 (one 4-chunk wave)
    float xpart[8] = {};  // ||x||^2 partials per owned row-slot

    auto issue_wave = [&](int kc, int base) {
        #pragma unroll
        for (int j = 0; j < 4; j++) {
            int r = r0 + (base + j) * 16;
            w[j] = ldg128(asrc0 + (size_t)r * DIM + kc * KC + cpos * 4);
        }
    };
    auto convert_wave = [&](int bf, int base) {
        uint32_t Ab = sb + AHF_OFF + bf * AHF_BYTES;
        #pragma unroll
        for (int j = 0; j < 4; j++) {
            int r = r0 + (base + j) * 16;
            uint32_t swz = (uint32_t)(r & 7) << 4;
            xpart[base + j] += w[j].x * w[j].x + w[j].y * w[j].y
                             + w[j].z * w[j].z + w[j].w * w[j].w;
            sts_v2(Ab + r * 128 + (((cpos >> 1) * 16) ^ swz) + (cpos & 1) * 8,
                   pack_f16(w[j].x, w[j].y), pack_f16(w[j].z, w[j].w));
        }
    };

    // ldmatrix lane addressing
    int ri = lane & 7;
    uint32_t mask = (uint32_t)ri << 4;
    uint32_t a_row0 = (uint32_t)(warp_m * 64 + ((lane >> 3) & 1) * 8 + ri) * 128;
    uint32_t akoff  = (uint32_t)(lane >> 4) * 16;
    uint32_t b_row0 = (uint32_t)(warp_n * 64 + (lane >> 4) * 8 + ri) * 128;
    uint32_t bkoff  = (uint32_t)((lane >> 3) & 1) * 16;

    uint32_t acc[4][8][2] = {};   // warp tile 64x64, f16x2 accumulators

    // ---- Prologue: build Ahf[0] for kc=0, stage B0/B1, prefetch A(kc=1) w1.
    issue_wave(0, 0); convert_wave(0, 0);
    issue_wave(0, 4); convert_wave(0, 4);
    load_B(0, 0);
    load_B(1, 1);
    if (NUM_KC > 1) issue_wave(1, 0);
    cp_wait<1>();                 // B0 done
    __syncthreads();              // Ahf0 + B0 visible

    for (int kc = 0; kc < NUM_KC; kc++) {
        int s = kc & 1;
        uint32_t Ab = sb + AHF_OFF + s * AHF_BYTES;
        uint32_t Bb = sb + B_OFF + s * B_BYTES;
        bool more = (kc + 1 < NUM_KC);

        #pragma unroll
        for (int ks = 0; ks < 4; ks++) {
            if (ks == 1 && more) {
                convert_wave(s ^ 1, 0);       // A[kc+1] wave1 -> Ahf[s^1]
                issue_wave(kc + 1, 4);        // prefetch wave2
            }
            if (ks == 3 && more) {
                convert_wave(s ^ 1, 4);       // A[kc+1] wave2
            }
            uint32_t a[4][4], b[4][4];
            uint32_t akb = (akoff + ks * 32) ^ mask;
            uint32_t bkb = (bkoff + ks * 32) ^ mask;
            #pragma unroll
            for (int mt = 0; mt < 4; mt++)
                ldsm4(a[mt], Ab + a_row0 + (uint32_t)(mt * 2048) + akb);
            #pragma unroll
            for (int gg = 0; gg < 4; gg++)
                ldsm4(b[gg], Bb + b_row0 + (uint32_t)(gg * 2048) + bkb);
            #pragma unroll
            for (int mt = 0; mt < 4; mt++)
                #pragma unroll
                for (int nt = 0; nt < 8; nt++)
                    mma16816h(acc[mt][nt], a[mt], b[nt >> 1] + (nt & 1) * 2);
        }

        cp_wait<0>();                         // B[kc+1] done
        __syncthreads();                      // publish Ahf[s^1] + B[kc+1]
        if (kc + 2 < NUM_KC) {
            issue_wave(kc + 2, 0);            // prefetch A[kc+2] wave1
            load_B(kc + 2, s);                // refill freed B stage
        }
    }

    // ---------------- Epilogue ----------------
    #pragma unroll
    for (int i = 0; i < 8; i++) x2p[(r0 + i * 16) * 16 + cpos] = xpart[i];
    __syncthreads();
    if (tid < TM) {
        float s = 0.f;
        #pragma unroll
        for (int j = 0; j < 16; j++) s += x2p[tid * 16 + j];
        x2s[tid] = s;
    }
    __syncthreads();

    int g = lane >> 2, qa = lane & 3;

    // Pass 1: row-sums of q (recompute q later; saves scratch registers)
    float rs[4][2];
    #pragma unroll
    for (int mt = 0; mt < 4; mt++) {
        #pragma unroll
        for (int h = 0; h < 2; h++) {
            int row = warp_m * 64 + mt * 16 + h * 8 + g;
            float x2v = x2s[row];
            float p = 0.f;
            #pragma unroll
            for (int nt = 0; nt < 8; nt++) {
                int col = warp_n * 64 + nt * 8 + qa * 2;
                union { uint32_t u; __half2 h2; } cvt;
                cvt.u = acc[mt][nt][h];
                float2 d = __half22float2(cvt.h2);
                p += frcp(1.f + fmaxf(fmaf(-2.f, d.x, x2v + c2s[col]), 0.f));
                p += frcp(1.f + fmaxf(fmaf(-2.f, d.y, x2v + c2s[col + 1]), 0.f));
            }
            rs[mt][h] = p;
        }
    }
    #pragma unroll
    for (int mt = 0; mt < 4; mt++)
        #pragma unroll
        for (int h = 0; h < 2; h++) {
            rs[mt][h] += __shfl_xor_sync(0xffffffffu, rs[mt][h], 1);
            rs[mt][h] += __shfl_xor_sync(0xffffffffu, rs[mt][h], 2);
        }
    if (qa == 0) {
        #pragma unroll
        for (int mt = 0; mt < 4; mt++)
            #pragma unroll
            for (int h = 0; h < 2; h++)
                red[(warp_m * 64 + mt * 16 + h * 8 + g) * 4 + warp_n] = rs[mt][h];
    }
    __syncthreads();

    float L = 0.f;
    if (tid < TM) {
        L = red[tid * 4] + red[tid * 4 + 1] + red[tid * 4 + 2] + red[tid * 4 + 3];
        uint32_t paddr;
        asm volatile("mapa.shared::cluster.u32 %0, %1, %2;"
                     : "=r"(paddr) : "r"(sb + PEER_OFF + tid * 4), "r"(nhalf ^ 1));
        asm volatile("st.shared::cluster.f32 [%0], %1;" :: "r"(paddr), "f"(L) : "memory");
    }
    asm volatile("barrier.cluster.arrive.aligned;" ::: "memory");
    asm volatile("barrier.cluster.wait.aligned;" ::: "memory");
    if (tid < TM) invs[tid] = frcp(L + peer[tid]);
    __syncthreads();

    // Pass 2: recompute q, normalize, store
    float* outbase = out + (size_t)mtile * TM * NCLU + nhalf * TN;
    #pragma unroll
    for (int mt = 0; mt < 4; mt++) {
        #pragma unroll
        for (int h = 0; h < 2; h++) {
            int row = warp_m * 64 + mt * 16 + h * 8 + g;
            float x2v = x2s[row];
            float inv = invs[row];
            float* orow = outbase + (size_t)row * NCLU + warp_n * 64;
            #pragma unroll
            for (int nt = 0; nt < 8; nt++) {
                int col = warp_n * 64 + nt * 8 + qa * 2;
                union { uint32_t u; __half2 h2; } cvt;
                cvt.u = acc[mt][nt][h];
                float2 d = __half22float2(cvt.h2);
                float2 v;
                v.x = frcp(1.f + fmaxf(fmaf(-2.f, d.x, x2v + c2s[col]), 0.f)) * inv;
                v.y = frcp(1.f + fmaxf(fmaf(-2.f, d.y, x2v + c2s[col + 1]), 0.f)) * inv;
                *(float2*)(orow + nt * 8 + qa * 2) = v;
            }
        }
    }
}

// ---------------------------------------------------------------------------
// Launch
// ---------------------------------------------------------------------------
extern "C" void kernel_launch(void* const* d_in, const int* in_sizes, int n_in,
                              void* d_out, int out_size) {
    const float* x  = (const float*)d_in[0];
    const float* cc = (const float*)d_in[1];
    float* out = (float*)d_out;

    cudaFuncSetAttribute(gemm_kernel,
                         cudaFuncAttributeMaxDynamicSharedMemorySize, SMEM_TOTAL);

    prep_c_kernel<<<NCLU / 8, 256>>>(cc);
    gemm_kernel<<<(N_ROWS / TM) * 2, 256, SMEM_TOTAL>>>(x, out);
}

// round 12
// speedup vs baseline: 1.8597x; 1.8597x over previous
#include <cuda_runtime.h>
#include <cuda_fp16.h>
#include <cstdint>
#include <cstddef>

#define N_ROWS 131072
#define DIM    512
#define NCLU   512

// ---------------------------------------------------------------------------
// Device-global scratch (centers only)
// ---------------------------------------------------------------------------
__device__ __half g_ch[(size_t)NCLU * DIM];
__device__ float g_c2[NCLU];

// ---------------------------------------------------------------------------
// Helpers
// ---------------------------------------------------------------------------
__device__ __forceinline__ uint32_t smem_to_u32(const void* smem_ptr) {
    uint32_t addr;
    asm("{ .reg .u64 tmp; cvta.to.shared.u64 tmp, %1; cvt.u32.u64 %0, tmp; }"
        : "=r"(addr) : "l"(smem_ptr));
    return addr;
}
__device__ __forceinline__ void cp16(uint32_t dst_smem, const void* src) {
    asm volatile("cp.async.cg.shared.global [%0], [%1], 16;"
                 :: "r"(dst_smem), "l"(src));
}
__device__ __forceinline__ void cp_commit() {
    asm volatile("cp.async.commit_group;");
}
template <int N>
__device__ __forceinline__ void cp_wait() {
    asm volatile("cp.async.wait_group %0;" :: "n"(N));
}
__device__ __forceinline__ float frcp(float a) {
    float r;
    asm("rcp.approx.f32 %0, %1;" : "=f"(r) : "f"(a));
    return r;
}
__device__ __forceinline__ void ldsm4(uint32_t* r, uint32_t addr) {
    asm volatile("ldmatrix.sync.aligned.m8n8.x4.shared.b16 {%0,%1,%2,%3}, [%4];"
                 : "=r"(r[0]), "=r"(r[1]), "=r"(r[2]), "=r"(r[3]) : "r"(addr));
}
__device__ __forceinline__ float4 lds_f4(uint32_t addr) {
    float4 v;
    asm volatile("ld.shared.v4.f32 {%0,%1,%2,%3}, [%4];"
                 : "=f"(v.x), "=f"(v.y), "=f"(v.z), "=f"(v.w) : "r"(addr));
    return v;
}
__device__ __forceinline__ void sts_v2(uint32_t addr, uint32_t a, uint32_t b) {
    asm volatile("st.shared.v2.b32 [%0], {%1,%2};"
                 :: "r"(addr), "r"(a), "r"(b) : "memory");
}
__device__ __forceinline__ void mma16816h(uint32_t* c, const uint32_t* a, const uint32_t* b) {
    asm volatile(
        "mma.sync.aligned.m16n8k16.row.col.f16.f16.f16.f16 "
        "{%0,%1}, {%2,%3,%4,%5}, {%6,%7}, {%0,%1};"
        : "+r"(c[0]), "+r"(c[1])
        : "r"(a[0]), "r"(a[1]), "r"(a[2]), "r"(a[3]), "r"(b[0]), "r"(b[1]));
}
__device__ __forceinline__ uint32_t pack_f16(float a, float b) {
    union { __half2 h; uint32_t u; } pk;
    pk.h = __floats2half2_rn(a, b);
    return pk.u;
}
// Scoped named barriers (memory-ordering semantics like bar.sync 0)
__device__ __forceinline__ void barg(int id) {
    asm volatile("bar.sync %0, 256;" :: "r"(id) : "memory");
}
__device__ __forceinline__ void barp(int id) {
    asm volatile("bar.sync %0, 64;" :: "r"(id) : "memory");
}

// ---------------------------------------------------------------------------
// Prep centers: fp32 -> fp16 + row norms (one row per warp). ~2us.
// ---------------------------------------------------------------------------
__global__ void prep_c_kernel(const float* __restrict__ c) {
    int row = blockIdx.x * 8 + (threadIdx.x >> 5);
    if (row >= NCLU) return;
    int lane = threadIdx.x & 31;
    const float4* sr = (const float4*)(c + (size_t)row * DIM);
    uint2* dr = (uint2*)(g_ch + (size_t)row * DIM);
    float s = 0.f;
    #pragma unroll
    for (int t = 0; t < 4; t++) {
        float4 v = sr[lane + 32 * t];
        s += v.x * v.x + v.y * v.y + v.z * v.z + v.w * v.w;
        uint2 u;
        u.x = pack_f16(v.x, v.y);
        u.y = pack_f16(v.z, v.w);
        dr[lane + 32 * t] = u;
    }
    #pragma unroll
    for (int o = 16; o; o >>= 1) s += __shfl_xor_sync(0xffffffffu, s, o);
    if (lane == 0) g_c2[row] = s;
}

// ---------------------------------------------------------------------------
// Fused GEMM + t-student epilogue, 512 threads / 16 warps, CTA tile 128x512,
// warp tile 64x64 (wg: 2 A-stripes x wn: 8 B-columns).
// NO CTA-wide barrier in the mainloop: per-warp cp.async groups + scoped
// named barriers (A-stripe group of 8 warps spread across SMSPs; B pair of
// 2 warps). Warps free-run so smem bursts and HMMA bursts overlap.
// ---------------------------------------------------------------------------
static constexpr int TM = 128, KC = 64, NUM_KC = DIM / KC;  // 8
static constexpr int AF_BYTES  = TM * KC * 4;               // 32768 (1 buf)
static constexpr int AHF_BYTES = TM * KC * 2;               // 16384 / buf
static constexpr int B_BYTES   = NCLU * KC * 2;             // 65536 / stage
static constexpr int AF_OFF   = 0;
static constexpr int AHF_OFF  = AF_BYTES;                    // 32768, 2 bufs
static constexpr int B_OFF    = AHF_OFF + 2 * AHF_BYTES;     // 65536, 2 stages
static constexpr int C2_OFF   = B_OFF + 2 * B_BYTES;         // 196608
static constexpr int X2_OFF   = C2_OFF + NCLU * 4;           // 198656
static constexpr int RED_OFF  = X2_OFF + TM * 4;             // 199168 (128x8)
static constexpr int INV_OFF  = RED_OFF + TM * 8 * 4;        // 203264
static constexpr int SMEM_TOTAL = INV_OFF + TM * 4;          // 203776

__global__ void __launch_bounds__(512, 1)
gemm_kernel(const float* __restrict__ x, float* __restrict__ out) {
    extern __shared__ __align__(1024) char smem[];
    uint32_t sb = smem_to_u32(smem);
    int tid = threadIdx.x;
    int wid = tid >> 5, lane = tid & 31;
    int mtile = blockIdx.x;
    // SMSP-balanced mapping: each SMSP hosts 2 warps of each A-group.
    int wg = (wid >> 2) & 1;                       // A-stripe group (0/1)
    int wn = (wid & 3) | ((wid >> 3) << 2);        // B column group (0..7)

    float* c2s  = (float*)(smem + C2_OFF);
    float* x2s  = (float*)(smem + X2_OFF);
    float* red  = (float*)(smem + RED_OFF);
    float* invs = (float*)(smem + INV_OFF);

    for (int i = tid; i < NCLU; i += 512) c2s[i] = g_c2[i];
    __syncthreads();   // c2s ready before any warp reaches its epilogue

    const float* asrc0 = x + (size_t)mtile * TM * DIM;

    // ---- A ownership: row ar (fixed per thread), 4 fp32-chunks per kc ----
    int ar = wg * 64 + wn * 8 + (lane >> 2);       // 128 rows covered
    int ac0 = lane & 3;                            // chunk col (of 16)
    uint32_t aswz = (uint32_t)(ar & 7) << 4;

    auto load_GA = [&](int kc) {
        const float* ap = asrc0 + (size_t)ar * DIM + kc * KC;
        uint32_t AfR = sb + AF_OFF + (uint32_t)ar * 256;
        #pragma unroll
        for (int i = 0; i < 4; i++) {
            int c = ac0 + 4 * i;
            cp16(AfR + (((uint32_t)c * 16) ^ aswz), ap + c * 4);
        }
        cp_commit();
    };
    // ---- B ownership: pair (wg0,wg1) of same wn covers rows wn*64..+63 ----
    auto load_GB = [&](int kc) {
        uint32_t Bb = sb + B_OFF + (kc & 1) * B_BYTES;
        const __half* bp = g_ch + kc * KC;
        #pragma unroll
        for (int i = 0; i < 8; i++) {
            int br = wn * 64 + wg * 32 + (lane >> 3) + 4 * i;
            int c = lane & 7;
            cp16(Bb + (uint32_t)br * 128 + (((uint32_t)c * 16) ^ ((uint32_t)(br & 7) << 4)),
                 bp + (size_t)br * DIM + c * 8);
        }
        cp_commit();
    };

    float xacc = 0.f;   // exact fp32 ||x||^2 partial for row ar

    auto convert = [&](int buf) {   // AF (own slots) -> Ahf[buf]
        uint32_t AfR = sb + AF_OFF + (uint32_t)ar * 256;
        uint32_t AbR = sb + AHF_OFF + buf * AHF_BYTES + (uint32_t)ar * 128;
        #pragma unroll
        for (int i = 0; i < 4; i++) {
            int c = ac0 + 4 * i;
            float4 v = lds_f4(AfR + (((uint32_t)c * 16) ^ aswz));
            xacc += v.x * v.x + v.y * v.y + v.z * v.z + v.w * v.w;
            sts_v2(AbR + ((((uint32_t)(c >> 1)) * 16) ^ aswz) + (c & 1) * 8,
                   pack_f16(v.x, v.y), pack_f16(v.z, v.w));
        }
    };

    // ldmatrix lane addressing
    int ri = lane & 7;
    uint32_t mask = (uint32_t)ri << 4;
    uint32_t a_row0 = (uint32_t)(wg * 64 + ((lane >> 3) & 1) * 8 + ri) * 128;
    uint32_t akoff  = (uint32_t)(lane >> 4) * 16;
    uint32_t b_row0 = (uint32_t)(wn * 64 + (lane >> 4) * 8 + ri) * 128;
    uint32_t bkoff  = (uint32_t)((lane >> 3) & 1) * 16;

    uint32_t acc[4][8][2] = {};   // warp tile 64x64, f16x2 accumulators

    int idg = 1 + wg;     // named barrier ids: A groups 1,2
    int idp = 3 + wn;     // B pairs 3..10

    // ---- Prologue (per warp) ----
    load_GA(0); load_GB(0);       // NOTE: two groups (each lambda commits)
    load_GB(1);
    cp_wait<1>();                 // GA0 + GB0 done (own)
    convert(0);                   // AF(A0) -> Ahf[0]; AF slots free
    load_GA(1);                   // A1 -> AF
    barg(idg); barp(idp);         // publish Ahf[0] + B[0]

    for (int kc = 0; kc < NUM_KC; kc++) {
        int s = kc & 1;
        uint32_t Ab = sb + AHF_OFF + s * AHF_BYTES;
        uint32_t Bb = sb + B_OFF + s * B_BYTES;

        #pragma unroll
        for (int ks = 0; ks < 4; ks++) {
            if (ks == 1 && kc < NUM_KC - 1) {
                cp_wait<0>();                 // GA(kc+1), GB(kc+1) done (own)
                convert(s ^ 1);               // A(kc+1) -> Ahf[s^1]
                if (kc + 2 < NUM_KC) load_GA(kc + 2);   // AF reusable (self)
            }
            uint32_t a[4][4], b[4][4];
            uint32_t akb = (akoff + ks * 32) ^ mask;
            uint32_t bkb = (bkoff + ks * 32) ^ mask;
            #pragma unroll
            for (int mt = 0; mt < 4; mt++)
                ldsm4(a[mt], Ab + a_row0 + (uint32_t)(mt * 2048) + akb);
            #pragma unroll
            for (int gg = 0; gg < 4; gg++)
                ldsm4(b[gg], Bb + b_row0 + (uint32_t)(gg * 2048) + bkb);
            #pragma unroll
            for (int mt = 0; mt < 4; mt++)
                #pragma unroll
                for (int nt = 0; nt < 8; nt++)
                    mma16816h(acc[mt][nt], a[mt], b[nt >> 1] + (nt & 1) * 2);
        }

        barg(idg);                // group done with Ahf[s]; Ahf[s^1] published
        barp(idp);                // pair done with B[s]
        if (kc + 2 < NUM_KC) load_GB(kc + 2);   // refill freed B[s]
    }

    // ---------------- Epilogue ----------------
    // ||x||^2: row ar shared by this thread's quad -> quad reduce
    xacc += __shfl_xor_sync(0xffffffffu, xacc, 1);
    xacc += __shfl_xor_sync(0xffffffffu, xacc, 2);
    if ((lane & 3) == 0) x2s[ar] = xacc;
    __syncthreads();

    int g = lane >> 2, qa = lane & 3;

    // Pass 1: row-sums of q
    float rs[4][2];
    #pragma unroll
    for (int mt = 0; mt < 4; mt++) {
        #pragma unroll
        for (int h = 0; h < 2; h++) {
            int row = wg * 64 + mt * 16 + h * 8 + g;
            float x2v = x2s[row];
            float p = 0.f;
            #pragma unroll
            for (int nt = 0; nt < 8; nt++) {
                int col = wn * 64 + nt * 8 + qa * 2;
                union { uint32_t u; __half2 h2; } cvt;
                cvt.u = acc[mt][nt][h];
                float2 d = __half22float2(cvt.h2);
                p += frcp(1.f + fmaxf(fmaf(-2.f, d.x, x2v + c2s[col]), 0.f));
                p += frcp(1.f + fmaxf(fmaf(-2.f, d.y, x2v + c2s[col + 1]), 0.f));
            }
            rs[mt][h] = p;
        }
    }
    #pragma unroll
    for (int mt = 0; mt < 4; mt++)
        #pragma unroll
        for (int h = 0; h < 2; h++) {
            rs[mt][h] += __shfl_xor_sync(0xffffffffu, rs[mt][h], 1);
            rs[mt][h] += __shfl_xor_sync(0xffffffffu, rs[mt][h], 2);
        }
    if (qa == 0) {
        #pragma unroll
        for (int mt = 0; mt < 4; mt++)
            #pragma unroll
            for (int h = 0; h < 2; h++)
                red[(wg * 64 + mt * 16 + h * 8 + g) * 8 + wn] = rs[mt][h];
    }
    __syncthreads();
    if (tid < TM) {
        float L = 0.f;
        #pragma unroll
        for (int j = 0; j < 8; j++) L += red[tid * 8 + j];
        invs[tid] = frcp(L);
    }
    __syncthreads();

    // Pass 2: recompute q, normalize, store
    float* outbase = out + (size_t)mtile * TM * NCLU;
    #pragma unroll
    for (int mt = 0; mt < 4; mt++) {
        #pragma unroll
        for (int h = 0; h < 2; h++) {
            int row = wg * 64 + mt * 16 + h * 8 + g;
            float x2v = x2s[row];
            float inv = invs[row];
            float* orow = outbase + (size_t)row * NCLU + wn * 64;
            #pragma unroll
            for (int nt = 0; nt < 8; nt++) {
                int col = wn * 64 + nt * 8 + qa * 2;
                union { uint32_t u; __half2 h2; } cvt;
                cvt.u = acc[mt][nt][h];
                float2 d = __half22float2(cvt.h2);
                float2 v;
                v.x = frcp(1.f + fmaxf(fmaf(-2.f, d.x, x2v + c2s[col]), 0.f)) * inv;
                v.y = frcp(1.f + fmaxf(fmaf(-2.f, d.y, x2v + c2s[col + 1]), 0.f)) * inv;
                *(float2*)(orow + nt * 8 + qa * 2) = v;
            }
        }
    }
}

// ---------------------------------------------------------------------------
// Launch
// ---------------------------------------------------------------------------
extern "C" void kernel_launch(void* const* d_in, const int* in_sizes, int n_in,
                              void* d_out, int out_size) {
    const float* x  = (const float*)d_in[0];
    const float* cc = (const float*)d_in[1];
    float* out = (float*)d_out;

    cudaFuncSetAttribute(gemm_kernel,
                         cudaFuncAttributeMaxDynamicSharedMemorySize, SMEM_TOTAL);

    prep_c_kernel<<<NCLU / 8, 256>>>(cc);
    gemm_kernel<<<N_ROWS / TM, 512, SMEM_TOTAL>>>(x, out);
}